// round 9
// baseline (speedup 1.0000x reference)
#include <cuda_runtime.h>
#include <cuda_fp16.h>
#include <cstdint>

#define ZD            16
#define KN            64
#define NTHREADS      256
#define WARPS         8
#define TPW           16                       // 16-row blocks per warp
#define ROWS_PER_WARP (TPW * 16)               // 256
#define ROWS_PER_CTA  (WARPS * ROWS_PER_WARP)  // 2048

// ---- helpers ---------------------------------------------------------------
__device__ __forceinline__ uint32_t pack_h2(float lo, float hi) {
    uint32_t r;
    asm("cvt.rn.f16x2.f32 %0, %1, %2;" : "=r"(r) : "f"(hi), "f"(lo));
    return r;
}
// split float pair into fp16x2 hi part and fp16x2 residual
__device__ __forceinline__ void split_h2(float x, float y, uint32_t& hi, uint32_t& lo) {
    uint32_t h = pack_h2(x, y);
    __half2 hh = *reinterpret_cast<__half2*>(&h);
    float2 hf = __half22float2(hh);
    hi = h;
    lo = pack_h2(x - hf.x, y - hf.y);
}
__device__ __forceinline__ float tanh_a(float x) {
    float r;
    asm("tanh.approx.f32 %0, %1;" : "=f"(r) : "f"(x));
    return r;
}
// fp16 MMA, fp32 accum, C given
__device__ __forceinline__ void mma_h(float* d, const uint32_t* a,
                                      uint32_t b0, uint32_t b1,
                                      const float* c) {
    asm("mma.sync.aligned.m16n8k16.row.col.f32.f16.f16.f32 "
        "{%0,%1,%2,%3}, {%4,%5,%6,%7}, {%8,%9}, {%10,%11,%12,%13};"
        : "=f"(d[0]), "=f"(d[1]), "=f"(d[2]), "=f"(d[3])
        : "r"(a[0]), "r"(a[1]), "r"(a[2]), "r"(a[3]),
          "r"(b0), "r"(b1),
          "f"(c[0]), "f"(c[1]), "f"(c[2]), "f"(c[3]));
}
// first MMA: C preloaded with {dk0, dk1, dk0, dk1} (free dk add)
__device__ __forceinline__ void mma_h_init(float* d, const uint32_t* a,
                                           uint32_t b0, uint32_t b1,
                                           float c0, float c1) {
    asm("mma.sync.aligned.m16n8k16.row.col.f32.f16.f16.f32 "
        "{%0,%1,%2,%3}, {%4,%5,%6,%7}, {%8,%9}, {%10,%11,%12,%13};"
        : "=f"(d[0]), "=f"(d[1]), "=f"(d[2]), "=f"(d[3])
        : "r"(a[0]), "r"(a[1]), "r"(a[2]), "r"(a[3]),
          "r"(b0), "r"(b1),
          "f"(c0), "f"(c1), "f"(c0), "f"(c1));
}

// ---- main kernel -----------------------------------------------------------
__global__ void __launch_bounds__(NTHREADS, 3) mave_mma(
    const float* __restrict__ z, const float* __restrict__ a0p,
    const float* __restrict__ bkp, const float* __restrict__ ck,
    const float* __restrict__ dkp, float* __restrict__ out)
{
    // sdb[j*4 + qid] = {dk[c0], bk[c0], dk[c1], bk[c1]}, c0 = j*8 + qid*2
    __shared__ float4 sdb[KN / 2];

    const int tid  = threadIdx.x;
    const int wid  = tid >> 5;
    const int lane = tid & 31;
    const int quad = lane >> 2;     // 0..7
    const int qid  = lane & 3;      // 0..3

    if (tid < KN / 2) {
        float4 v;
        v.x = dkp[2 * tid];     v.y = bkp[2 * tid];
        v.z = dkp[2 * tid + 1]; v.w = bkp[2 * tid + 1];
        sdb[tid] = v;
    }
    __syncthreads();
    const float a0 = a0p[0];

    // constant B fragments (ck fp16 hi + fp16 residual), 8 n-tiles, 32 regs
    uint32_t bh[8][2], bl[8][2];
    #pragma unroll
    for (int j = 0; j < 8; ++j) {
        const float* cr = ck + (j * 8 + quad) * ZD + qid * 2;
        float2 g0 = *reinterpret_cast<const float2*>(cr);
        float2 g1 = *reinterpret_cast<const float2*>(cr + 8);
        split_h2(g0.x, g0.y, bh[j][0], bl[j][0]);
        split_h2(g1.x, g1.y, bh[j][1], bl[j][1]);
    }

    const long warp_base = (long)blockIdx.x * ROWS_PER_CTA + (long)wid * ROWS_PER_WARP;
    // fragment base: row = base + quad, k = qid*2
    const float* zp = z + (warp_base + quad) * ZD + qid * 2;

    // prefetch block 0
    float2 p0 = *reinterpret_cast<const float2*>(zp);
    float2 p1 = *reinterpret_cast<const float2*>(zp + 8 * ZD);
    float2 p2 = *reinterpret_cast<const float2*>(zp + 8);
    float2 p3 = *reinterpret_cast<const float2*>(zp + 8 * ZD + 8);

    #pragma unroll 1
    for (int blk = 0; blk < TPW; ++blk) {
        // A fragments: plain fp16 (no residual needed at fp16 precision)
        uint32_t a16[4];
        a16[0] = pack_h2(p0.x, p0.y);
        a16[1] = pack_h2(p1.x, p1.y);
        a16[2] = pack_h2(p2.x, p2.y);
        a16[3] = pack_h2(p3.x, p3.y);

        if (blk + 1 < TPW) {   // prefetch next block while MMAs run
            const float* zn = zp + (long)(blk + 1) * 16 * ZD;
            p0 = *reinterpret_cast<const float2*>(zn);
            p1 = *reinterpret_cast<const float2*>(zn + 8 * ZD);
            p2 = *reinterpret_cast<const float2*>(zn + 8);
            p3 = *reinterpret_cast<const float2*>(zn + 8 * ZD + 8);
        }

        float acc0 = 0.f, acc1 = 0.f, acc2 = 0.f, acc3 = 0.f;

        #pragma unroll
        for (int j = 0; j < 8; ++j) {
            float4 q = sdb[j * 4 + qid];   // LDS.128, quad-uniform broadcast
            float d[4];
            mma_h_init(d, a16, bh[j][0], bh[j][1], q.x, q.z);  // z_h*c_h + dk
            mma_h(d, a16, bl[j][0], bl[j][1], d);              // z_h*c_l

            acc0 = fmaf(tanh_a(d[0]), q.y, acc0);
            acc1 = fmaf(tanh_a(d[1]), q.w, acc1);
            acc2 = fmaf(tanh_a(d[2]), q.y, acc2);
            acc3 = fmaf(tanh_a(d[3]), q.w, acc3);
        }

        float r0 = acc0 + acc1;   // row quad
        float r1 = acc2 + acc3;   // row quad + 8
        r0 += __shfl_xor_sync(0xFFFFFFFFu, r0, 1);
        r0 += __shfl_xor_sync(0xFFFFFFFFu, r0, 2);
        r1 += __shfl_xor_sync(0xFFFFFFFFu, r1, 1);
        r1 += __shfl_xor_sync(0xFFFFFFFFu, r1, 2);

        if (qid == 0) {
            const long row = warp_base + (long)blk * 16 + quad;
            out[row]     = a0 + r0;
            out[row + 8] = a0 + r1;
        }
    }
}

// ---- scalar tail (unused when B % 2048 == 0; B = 2M is) --------------------
__global__ void mave_tail(
    const float* __restrict__ z, const float* __restrict__ a0p,
    const float* __restrict__ bk, const float* __restrict__ ck,
    const float* __restrict__ dk, float* __restrict__ out,
    long start, long Btot)
{
    long row = start + (long)blockIdx.x * blockDim.x + threadIdx.x;
    if (row >= Btot) return;
    const float* zr = z + row * ZD;
    float zv[ZD];
    #pragma unroll
    for (int i = 0; i < ZD; ++i) zv[i] = zr[i];
    float acc = a0p[0];
    for (int k = 0; k < KN; ++k) {
        float h = dk[k];
        #pragma unroll
        for (int zi = 0; zi < ZD; ++zi) h = fmaf(ck[k * ZD + zi], zv[zi], h);
        acc = fmaf(bk[k], tanh_a(h), acc);
    }
    out[row] = acc;
}

extern "C" void kernel_launch(void* const* d_in, const int* in_sizes, int n_in,
                              void* d_out, int out_size) {
    const float* z  = (const float*)d_in[0];
    const float* a0 = (const float*)d_in[1];
    const float* bk = (const float*)d_in[2];
    const float* ck = (const float*)d_in[3];
    const float* dk = (const float*)d_in[4];
    float* out = (float*)d_out;

    const long B = (long)in_sizes[0] / ZD;
    const long nfull = B / ROWS_PER_CTA;

    if (nfull > 0) {
        mave_mma<<<(int)nfull, NTHREADS>>>(z, a0, bk, ck, dk, out);
    }
    const long rem = B - nfull * ROWS_PER_CTA;
    if (rem > 0) {
        mave_tail<<<(int)((rem + 255) / 256), 256>>>(z, a0, bk, ck, dk, out,
                                                     nfull * ROWS_PER_CTA, B);
    }
}

// round 11
// speedup vs baseline: 1.5406x; 1.5406x over previous
#include <cuda_runtime.h>
#include <cuda_fp16.h>
#include <cstdint>

#define ZD            16
#define KN            64
#define NTHREADS      256
#define WARPS         8
#define TPW           16                       // 16-row blocks per warp
#define ROWS_PER_WARP (TPW * 16)               // 256
#define ROWS_PER_CTA  (WARPS * ROWS_PER_WARP)  // 2048

// ---- helpers ---------------------------------------------------------------
__device__ __forceinline__ uint32_t pack_h2(float lo, float hi) {
    uint32_t r;
    asm("cvt.rn.f16x2.f32 %0, %1, %2;" : "=r"(r) : "f"(hi), "f"(lo));
    return r;
}
// split float pair into fp16x2 hi part and fp16x2 residual
__device__ __forceinline__ void split_h2(float x, float y, uint32_t& hi, uint32_t& lo) {
    uint32_t h = pack_h2(x, y);
    __half2 hh = *reinterpret_cast<__half2*>(&h);
    float2 hf = __half22float2(hh);
    hi = h;
    lo = pack_h2(x - hf.x, y - hf.y);
}
__device__ __forceinline__ float tanh_a(float x) {
    float r;
    asm("tanh.approx.f32 %0, %1;" : "=f"(r) : "f"(x));
    return r;
}
// fp16 MMA, fp32 accum, C given
__device__ __forceinline__ void mma_h(float* d, const uint32_t* a,
                                      uint32_t b0, uint32_t b1,
                                      const float* c) {
    asm("mma.sync.aligned.m16n8k16.row.col.f32.f16.f16.f32 "
        "{%0,%1,%2,%3}, {%4,%5,%6,%7}, {%8,%9}, {%10,%11,%12,%13};"
        : "=f"(d[0]), "=f"(d[1]), "=f"(d[2]), "=f"(d[3])
        : "r"(a[0]), "r"(a[1]), "r"(a[2]), "r"(a[3]),
          "r"(b0), "r"(b1),
          "f"(c[0]), "f"(c[1]), "f"(c[2]), "f"(c[3]));
}
// first MMA: C preloaded with {dk0, dk1, dk0, dk1} (free dk add)
__device__ __forceinline__ void mma_h_init(float* d, const uint32_t* a,
                                           uint32_t b0, uint32_t b1,
                                           float c0, float c1) {
    asm("mma.sync.aligned.m16n8k16.row.col.f32.f16.f16.f32 "
        "{%0,%1,%2,%3}, {%4,%5,%6,%7}, {%8,%9}, {%10,%11,%12,%13};"
        : "=f"(d[0]), "=f"(d[1]), "=f"(d[2]), "=f"(d[3])
        : "r"(a[0]), "r"(a[1]), "r"(a[2]), "r"(a[3]),
          "r"(b0), "r"(b1),
          "f"(c0), "f"(c1), "f"(c0), "f"(c1));
}

// ---- main kernel -----------------------------------------------------------
__global__ void __launch_bounds__(NTHREADS) mave_mma(
    const float* __restrict__ z, const float* __restrict__ a0p,
    const float* __restrict__ bkp, const float* __restrict__ ck,
    const float* __restrict__ dkp, float* __restrict__ out)
{
    // sdb[j*4 + qid] = {dk[c0], bk[c0], dk[c1], bk[c1]}, c0 = j*8 + qid*2
    __shared__ float4 sdb[KN / 2];

    const int tid  = threadIdx.x;
    const int wid  = tid >> 5;
    const int lane = tid & 31;
    const int quad = lane >> 2;     // 0..7
    const int qid  = lane & 3;      // 0..3

    if (tid < KN / 2) {
        float4 v;
        v.x = dkp[2 * tid];     v.y = bkp[2 * tid];
        v.z = dkp[2 * tid + 1]; v.w = bkp[2 * tid + 1];
        sdb[tid] = v;
    }
    __syncthreads();
    const float a0 = a0p[0];

    // constant B fragments (ck fp16 hi + fp16 residual), 8 n-tiles, 32 regs
    uint32_t bh[8][2], bl[8][2];
    #pragma unroll
    for (int j = 0; j < 8; ++j) {
        const float* cr = ck + (j * 8 + quad) * ZD + qid * 2;
        float2 g0 = *reinterpret_cast<const float2*>(cr);
        float2 g1 = *reinterpret_cast<const float2*>(cr + 8);
        split_h2(g0.x, g0.y, bh[j][0], bl[j][0]);
        split_h2(g1.x, g1.y, bh[j][1], bl[j][1]);
    }

    const long warp_base = (long)blockIdx.x * ROWS_PER_CTA + (long)wid * ROWS_PER_WARP;
    // fragment base: row = base + quad, k = qid*2
    const float* zp = z + (warp_base + quad) * ZD + qid * 2;

    // prefetch block 0
    float2 p0 = *reinterpret_cast<const float2*>(zp);
    float2 p1 = *reinterpret_cast<const float2*>(zp + 8 * ZD);
    float2 p2 = *reinterpret_cast<const float2*>(zp + 8);
    float2 p3 = *reinterpret_cast<const float2*>(zp + 8 * ZD + 8);

    #pragma unroll 1
    for (int blk = 0; blk < TPW; ++blk) {
        // A fragments: plain fp16 (no residual needed at fp16 precision)
        uint32_t a16[4];
        a16[0] = pack_h2(p0.x, p0.y);
        a16[1] = pack_h2(p1.x, p1.y);
        a16[2] = pack_h2(p2.x, p2.y);
        a16[3] = pack_h2(p3.x, p3.y);

        if (blk + 1 < TPW) {   // prefetch next block while MMAs run
            const float* zn = zp + (long)(blk + 1) * 16 * ZD;
            p0 = *reinterpret_cast<const float2*>(zn);
            p1 = *reinterpret_cast<const float2*>(zn + 8 * ZD);
            p2 = *reinterpret_cast<const float2*>(zn + 8);
            p3 = *reinterpret_cast<const float2*>(zn + 8 * ZD + 8);
        }

        float acc0 = 0.f, acc1 = 0.f, acc2 = 0.f, acc3 = 0.f;

        #pragma unroll
        for (int j = 0; j < 8; ++j) {
            float4 q = sdb[j * 4 + qid];   // LDS.128, quad-uniform broadcast
            float d[4];
            mma_h_init(d, a16, bh[j][0], bh[j][1], q.x, q.z);  // z_h*c_h + dk
            mma_h(d, a16, bl[j][0], bl[j][1], d);              // z_h*c_l

            acc0 = fmaf(tanh_a(d[0]), q.y, acc0);
            acc1 = fmaf(tanh_a(d[1]), q.w, acc1);
            acc2 = fmaf(tanh_a(d[2]), q.y, acc2);
            acc3 = fmaf(tanh_a(d[3]), q.w, acc3);
        }

        float r0 = acc0 + acc1;   // row quad
        float r1 = acc2 + acc3;   // row quad + 8
        r0 += __shfl_xor_sync(0xFFFFFFFFu, r0, 1);
        r0 += __shfl_xor_sync(0xFFFFFFFFu, r0, 2);
        r1 += __shfl_xor_sync(0xFFFFFFFFu, r1, 1);
        r1 += __shfl_xor_sync(0xFFFFFFFFu, r1, 2);

        if (qid == 0) {
            const long row = warp_base + (long)blk * 16 + quad;
            out[row]     = a0 + r0;
            out[row + 8] = a0 + r1;
        }
    }
}

// ---- scalar tail (unused when B % 2048 == 0; B = 2M is) --------------------
__global__ void mave_tail(
    const float* __restrict__ z, const float* __restrict__ a0p,
    const float* __restrict__ bk, const float* __restrict__ ck,
    const float* __restrict__ dk, float* __restrict__ out,
    long start, long Btot)
{
    long row = start + (long)blockIdx.x * blockDim.x + threadIdx.x;
    if (row >= Btot) return;
    const float* zr = z + row * ZD;
    float zv[ZD];
    #pragma unroll
    for (int i = 0; i < ZD; ++i) zv[i] = zr[i];
    float acc = a0p[0];
    for (int k = 0; k < KN; ++k) {
        float h = dk[k];
        #pragma unroll
        for (int zi = 0; zi < ZD; ++zi) h = fmaf(ck[k * ZD + zi], zv[zi], h);
        acc = fmaf(bk[k], tanh_a(h), acc);
    }
    out[row] = acc;
}

extern "C" void kernel_launch(void* const* d_in, const int* in_sizes, int n_in,
                              void* d_out, int out_size) {
    const float* z  = (const float*)d_in[0];
    const float* a0 = (const float*)d_in[1];
    const float* bk = (const float*)d_in[2];
    const float* ck = (const float*)d_in[3];
    const float* dk = (const float*)d_in[4];
    float* out = (float*)d_out;

    const long B = (long)in_sizes[0] / ZD;
    const long nfull = B / ROWS_PER_CTA;

    if (nfull > 0) {
        mave_mma<<<(int)nfull, NTHREADS>>>(z, a0, bk, ck, dk, out);
    }
    const long rem = B - nfull * ROWS_PER_CTA;
    if (rem > 0) {
        mave_tail<<<(int)((rem + 255) / 256), 256>>>(z, a0, bk, ck, dk, out,
                                                     nfull * ROWS_PER_CTA, B);
    }
}

// round 12
// speedup vs baseline: 1.8578x; 1.2059x over previous
#include <cuda_runtime.h>
#include <cuda_fp16.h>
#include <cstdint>

#define ZD            16
#define KN            64
#define NTHREADS      256
#define WARPS         8
#define TPW           8                        // iterations per warp (32 rows each)
#define ROWS_PER_WARP (TPW * 32)               // 256
#define ROWS_PER_CTA  (WARPS * ROWS_PER_WARP)  // 2048

// ---- helpers ---------------------------------------------------------------
__device__ __forceinline__ uint32_t pack_h2(float lo, float hi) {
    uint32_t r;
    asm("cvt.rn.f16x2.f32 %0, %1, %2;" : "=r"(r) : "f"(hi), "f"(lo));
    return r;
}
__device__ __forceinline__ float tanh_a(float x) {
    float r;
    asm("tanh.approx.f32 %0, %1;" : "=f"(r) : "f"(x));
    return r;
}
// fp16 MMA, fp32 accum, C preloaded with {dk0, dk1, dk0, dk1} (free dk add)
__device__ __forceinline__ void mma_h_init(float* d, const uint32_t* a,
                                           uint32_t b0, uint32_t b1,
                                           float c0, float c1) {
    asm("mma.sync.aligned.m16n8k16.row.col.f32.f16.f16.f32 "
        "{%0,%1,%2,%3}, {%4,%5,%6,%7}, {%8,%9}, {%10,%11,%12,%13};"
        : "=f"(d[0]), "=f"(d[1]), "=f"(d[2]), "=f"(d[3])
        : "r"(a[0]), "r"(a[1]), "r"(a[2]), "r"(a[3]),
          "r"(b0), "r"(b1),
          "f"(c0), "f"(c1), "f"(c0), "f"(c1));
}

// ---- main kernel -----------------------------------------------------------
__global__ void __launch_bounds__(NTHREADS) mave_mma(
    const float* __restrict__ z, const float* __restrict__ a0p,
    const float* __restrict__ bkp, const float* __restrict__ ck,
    const float* __restrict__ dkp, float* __restrict__ out)
{
    // sdb[j*4 + qid] = {dk[c0], bk[c0], dk[c1], bk[c1]}, c0 = j*8 + qid*2
    __shared__ float4 sdb[KN / 2];

    const int tid  = threadIdx.x;
    const int wid  = tid >> 5;
    const int lane = tid & 31;
    const int quad = lane >> 2;     // 0..7
    const int qid  = lane & 3;      // 0..3

    if (tid < KN / 2) {
        float4 v;
        v.x = dkp[2 * tid];     v.y = bkp[2 * tid];
        v.z = dkp[2 * tid + 1]; v.w = bkp[2 * tid + 1];
        sdb[tid] = v;
    }
    __syncthreads();
    const float a0 = a0p[0];

    // constant B fragments: ck as plain fp16 (no residual), 8 n-tiles, 16 regs
    uint32_t bh[8][2];
    #pragma unroll
    for (int j = 0; j < 8; ++j) {
        const float* cr = ck + (j * 8 + quad) * ZD + qid * 2;
        float2 g0 = *reinterpret_cast<const float2*>(cr);
        float2 g1 = *reinterpret_cast<const float2*>(cr + 8);
        bh[j][0] = pack_h2(g0.x, g0.y);
        bh[j][1] = pack_h2(g1.x, g1.y);
    }

    const long warp_base = (long)blockIdx.x * ROWS_PER_CTA + (long)wid * ROWS_PER_WARP;
    // fragment base: row = base + quad, k = qid*2
    const float* zp = z + (warp_base + quad) * ZD + qid * 2;

    // prefetch iteration 0 (two 16-row blocks: rows +0.. and +16..)
    float2 pA0 = *reinterpret_cast<const float2*>(zp);
    float2 pA1 = *reinterpret_cast<const float2*>(zp + 8 * ZD);
    float2 pA2 = *reinterpret_cast<const float2*>(zp + 8);
    float2 pA3 = *reinterpret_cast<const float2*>(zp + 8 * ZD + 8);
    float2 pB0 = *reinterpret_cast<const float2*>(zp + 16 * ZD);
    float2 pB1 = *reinterpret_cast<const float2*>(zp + 24 * ZD);
    float2 pB2 = *reinterpret_cast<const float2*>(zp + 16 * ZD + 8);
    float2 pB3 = *reinterpret_cast<const float2*>(zp + 24 * ZD + 8);

    #pragma unroll 1
    for (int blk = 0; blk < TPW; ++blk) {
        // A fragments for both blocks: plain fp16
        uint32_t aA[4], aB[4];
        aA[0] = pack_h2(pA0.x, pA0.y);
        aA[1] = pack_h2(pA1.x, pA1.y);
        aA[2] = pack_h2(pA2.x, pA2.y);
        aA[3] = pack_h2(pA3.x, pA3.y);
        aB[0] = pack_h2(pB0.x, pB0.y);
        aB[1] = pack_h2(pB1.x, pB1.y);
        aB[2] = pack_h2(pB2.x, pB2.y);
        aB[3] = pack_h2(pB3.x, pB3.y);

        if (blk + 1 < TPW) {   // prefetch next iteration while MMAs run
            const float* zn = zp + (long)(blk + 1) * 32 * ZD;
            pA0 = *reinterpret_cast<const float2*>(zn);
            pA1 = *reinterpret_cast<const float2*>(zn + 8 * ZD);
            pA2 = *reinterpret_cast<const float2*>(zn + 8);
            pA3 = *reinterpret_cast<const float2*>(zn + 8 * ZD + 8);
            pB0 = *reinterpret_cast<const float2*>(zn + 16 * ZD);
            pB1 = *reinterpret_cast<const float2*>(zn + 24 * ZD);
            pB2 = *reinterpret_cast<const float2*>(zn + 16 * ZD + 8);
            pB3 = *reinterpret_cast<const float2*>(zn + 24 * ZD + 8);
        }

        float accA0 = 0.f, accA1 = 0.f, accA2 = 0.f, accA3 = 0.f;
        float accB0 = 0.f, accB1 = 0.f, accB2 = 0.f, accB3 = 0.f;

        #pragma unroll
        for (int j = 0; j < 8; ++j) {
            float4 q = sdb[j * 4 + qid];   // one LDS.128 serves both blocks
            float dA[4], dB[4];
            mma_h_init(dA, aA, bh[j][0], bh[j][1], q.x, q.z);  // z*c + dk
            mma_h_init(dB, aB, bh[j][0], bh[j][1], q.x, q.z);

            accA0 = fmaf(tanh_a(dA[0]), q.y, accA0);
            accA1 = fmaf(tanh_a(dA[1]), q.w, accA1);
            accA2 = fmaf(tanh_a(dA[2]), q.y, accA2);
            accA3 = fmaf(tanh_a(dA[3]), q.w, accA3);
            accB0 = fmaf(tanh_a(dB[0]), q.y, accB0);
            accB1 = fmaf(tanh_a(dB[1]), q.w, accB1);
            accB2 = fmaf(tanh_a(dB[2]), q.y, accB2);
            accB3 = fmaf(tanh_a(dB[3]), q.w, accB3);
        }

        float rA0 = accA0 + accA1, rA1 = accA2 + accA3;   // rows quad, quad+8
        float rB0 = accB0 + accB1, rB1 = accB2 + accB3;   // rows quad+16, quad+24
        rA0 += __shfl_xor_sync(0xFFFFFFFFu, rA0, 1);
        rA0 += __shfl_xor_sync(0xFFFFFFFFu, rA0, 2);
        rA1 += __shfl_xor_sync(0xFFFFFFFFu, rA1, 1);
        rA1 += __shfl_xor_sync(0xFFFFFFFFu, rA1, 2);
        rB0 += __shfl_xor_sync(0xFFFFFFFFu, rB0, 1);
        rB0 += __shfl_xor_sync(0xFFFFFFFFu, rB0, 2);
        rB1 += __shfl_xor_sync(0xFFFFFFFFu, rB1, 1);
        rB1 += __shfl_xor_sync(0xFFFFFFFFu, rB1, 2);

        if (qid == 0) {
            const long r0 = warp_base + (long)blk * 32 + quad;
            out[r0]      = a0 + rA0;
            out[r0 + 8]  = a0 + rA1;
            out[r0 + 16] = a0 + rB0;
            out[r0 + 24] = a0 + rB1;
        }
    }
}

// ---- scalar tail (unused when B % 2048 == 0; B = 2M is) --------------------
__global__ void mave_tail(
    const float* __restrict__ z, const float* __restrict__ a0p,
    const float* __restrict__ bk, const float* __restrict__ ck,
    const float* __restrict__ dk, float* __restrict__ out,
    long start, long Btot)
{
    long row = start + (long)blockIdx.x * blockDim.x + threadIdx.x;
    if (row >= Btot) return;
    const float* zr = z + row * ZD;
    float zv[ZD];
    #pragma unroll
    for (int i = 0; i < ZD; ++i) zv[i] = zr[i];
    float acc = a0p[0];
    for (int k = 0; k < KN; ++k) {
        float h = dk[k];
        #pragma unroll
        for (int zi = 0; zi < ZD; ++zi) h = fmaf(ck[k * ZD + zi], zv[zi], h);
        acc = fmaf(bk[k], tanh_a(h), acc);
    }
    out[row] = acc;
}

extern "C" void kernel_launch(void* const* d_in, const int* in_sizes, int n_in,
                              void* d_out, int out_size) {
    const float* z  = (const float*)d_in[0];
    const float* a0 = (const float*)d_in[1];
    const float* bk = (const float*)d_in[2];
    const float* ck = (const float*)d_in[3];
    const float* dk = (const float*)d_in[4];
    float* out = (float*)d_out;

    const long B = (long)in_sizes[0] / ZD;
    const long nfull = B / ROWS_PER_CTA;

    if (nfull > 0) {
        mave_mma<<<(int)nfull, NTHREADS>>>(z, a0, bk, ck, dk, out);
    }
    const long rem = B - nfull * ROWS_PER_CTA;
    if (rem > 0) {
        mave_tail<<<(int)((rem + 255) / 256), 256>>>(z, a0, bk, ck, dk, out,
                                                     nfull * ROWS_PER_CTA, B);
    }
}